// round 11
// baseline (speedup 1.0000x reference)
#include <cuda_runtime.h>
#include <cuda_fp16.h>
#include <math.h>

#define N_NODES 100000
#define NUM_GRAPHS 128
#define H1 4
#define C1 48
#define F1 192   // H1*C1
#define C2 96
#define D_IN 128
#define NEG_SLOPE 0.2f
#define E_MAX 1750000   // raw edges (1.6M) + self loops (100k) with slack

// ---------------- scratch (device globals; no allocation) ----------------
__device__ __half g_h1h[N_NODES * F1];      // fp16 gather table (layer 1)
__device__ float g_h1r[N_NODES * F1];       // layer1 output (relu'd, fp32)
__device__ __half g_h2h[N_NODES * C2];      // fp16 gather table (layer 2)
__device__ float g_wa1[8 * D_IN];           // [o][k]: W1-contracted attn vectors (4 src + 4 dst)
__device__ float g_w2[2 * F1];              // [o][k]: W2-contracted attn vectors (src, dst)
__device__ float g_asrc1[N_NODES * H1];
__device__ float g_adst1[N_NODES * H1];
__device__ float g_asrc2[N_NODES];
__device__ float g_adst2[N_NODES];
__device__ float g_pool[NUM_GRAPHS * C2];
__device__ float g_cnt[NUM_GRAPHS];
__device__ int g_src[E_MAX];
__device__ int g_dst[E_MAX];
__device__ int g_batch[N_NODES];
__device__ int g_is64;
__device__ int g_deg[N_NODES];
__device__ int g_off[N_NODES + 1];
__device__ int g_cur[N_NODES];
__device__ int g_csr_src[E_MAX];
__device__ float g_p[E_MAX * H1];

__device__ __forceinline__ float leaky(float s) {
    return s > 0.0f ? s : NEG_SLOPE * s;
}

// ---------------- init (zero counters only) ----------------
__global__ void init_kernel() {
    int i = blockIdx.x * blockDim.x + threadIdx.x;
    int stride = gridDim.x * blockDim.x;
    for (int k = i; k < N_NODES; k += stride) g_deg[k] = 0;
    for (int k = i; k < NUM_GRAPHS * C2; k += stride) g_pool[k] = 0.0f;
    for (int k = i; k < NUM_GRAPHS; k += stride) g_cnt[k] = 0.0f;
}

// ---------------- dtype sniff: int64 vs int32 index buffers ----------------
__global__ void sniff_kernel(const unsigned int* __restrict__ w) {
    __shared__ int any_nonzero;
    if (threadIdx.x == 0) any_nonzero = 0;
    __syncthreads();
    for (int i = threadIdx.x; i < 256; i += blockDim.x) {
        if (w[2 * i + 1] != 0u) any_nonzero = 1;
    }
    __syncthreads();
    if (threadIdx.x == 0) g_is64 = (any_nonzero == 0) ? 1 : 0;
}

__global__ void decode_edges(const void* __restrict__ ei_raw, int E0) {
    int e = blockIdx.x * blockDim.x + threadIdx.x;
    int Etot = E0 + N_NODES;
    if (e >= Etot) return;
    int src, dst;
    if (e < E0) {
        if (g_is64) {
            const long long* p = (const long long*)ei_raw;
            src = (int)p[e];
            dst = (int)p[E0 + e];
        } else {
            const int* p = (const int*)ei_raw;
            src = p[e];
            dst = p[E0 + e];
        }
    } else {
        src = dst = e - E0;
    }
    g_src[e] = src;
    g_dst[e] = dst;
    atomicAdd(&g_deg[dst], 1);
}

__global__ void decode_batch(const void* __restrict__ b_raw) {
    __shared__ int hist[NUM_GRAPHS];
    for (int i = threadIdx.x; i < NUM_GRAPHS; i += blockDim.x) hist[i] = 0;
    __syncthreads();
    int n = blockIdx.x * blockDim.x + threadIdx.x;
    if (n < N_NODES) {
        int b = g_is64 ? (int)((const long long*)b_raw)[n] : ((const int*)b_raw)[n];
        g_batch[n] = b;
        atomicAdd(&hist[b], 1);
    }
    __syncthreads();
    for (int i = threadIdx.x; i < NUM_GRAPHS; i += blockDim.x)
        if (hist[i]) atomicAdd(&g_cnt[i], (float)hist[i]);
}

__global__ void scan_kernel() {
    __shared__ int part[1024];
    int t = threadIdx.x;
    const int CH = (N_NODES + 1023) / 1024;
    int lo = t * CH, hi = min(lo + CH, N_NODES);
    int s = 0;
    for (int i = lo; i < hi; i++) s += g_deg[i];
    part[t] = s;
    __syncthreads();
    for (int o = 1; o < 1024; o <<= 1) {
        int v = (t >= o) ? part[t - o] : 0;
        __syncthreads();
        part[t] += v;
        __syncthreads();
    }
    int base = (t > 0) ? part[t - 1] : 0;
    for (int i = lo; i < hi; i++) {
        g_off[i] = base;
        g_cur[i] = base;
        base += g_deg[i];
    }
    if (t == 1023) g_off[N_NODES] = part[1023];
}

__global__ void scatter_kernel(int Etot) {
    int e = blockIdx.x * blockDim.x + threadIdx.x;
    if (e >= Etot) return;
    int pos = atomicAdd(&g_cur[g_dst[e]], 1);
    g_csr_src[pos] = g_src[e];
}

// ---------------- attention-vector precompute (tiny) ------------------------
// g_wa1[o][k] = sum_j W1[k, (o&3)*48+j] * a_{src|dst}1[(o&3)*48+j]
__global__ void precomp1_kernel(const float* __restrict__ W1,
                                const float* __restrict__ a_src1,
                                const float* __restrict__ a_dst1) {
    int t = threadIdx.x;  // 1024 threads
    int k = t >> 3, o = t & 7;
    const float* w = &W1[k * F1 + (o & 3) * C1];
    const float* a = ((o < 4) ? a_src1 : a_dst1) + (o & 3) * C1;
    float s = 0.0f;
#pragma unroll
    for (int j = 0; j < C1; j++) s += w[j] * a[j];
    g_wa1[o * D_IN + k] = s;
}

// g_w2[o][k] = sum_j W2[k*96+j] * a_{src|dst}2[j]
__global__ void precomp2_kernel(const float* __restrict__ W2,
                                const float* __restrict__ a_src2,
                                const float* __restrict__ a_dst2) {
    int t = threadIdx.x;  // 384 threads
    int k = t % F1, o = t / F1;
    const float* a = o ? a_dst2 : a_src2;
    float s = 0.0f;
#pragma unroll
    for (int j = 0; j < C2; j++) s += W2[k * C2 + j] * a[j];
    g_w2[o * F1 + k] = s;
}

// ---------------- attention scalars straight from x / h1r -------------------
__global__ void attn1_kernel(const float* __restrict__ x) {
    __shared__ float sw[8 * D_IN];
    int tid = threadIdx.x;
    for (int i = tid; i < 8 * D_IN; i += 256) sw[i] = g_wa1[i];
    __syncthreads();
    int node = (blockIdx.x * 256 + tid) >> 5;
    int lane = tid & 31;
    if (node >= N_NODES) return;
    float4 xv = *(const float4*)&x[(size_t)node * D_IN + lane * 4];
    float acc[8];
#pragma unroll
    for (int o = 0; o < 8; o++) {
        float4 w = *(const float4*)&sw[o * D_IN + lane * 4];
        acc[o] = xv.x * w.x + xv.y * w.y + xv.z * w.z + xv.w * w.w;
    }
#pragma unroll
    for (int o = 0; o < 8; o++)
#pragma unroll
        for (int s = 16; s > 0; s >>= 1) acc[o] += __shfl_xor_sync(0xffffffffu, acc[o], s);
    if (lane == 0) {
        *(float4*)&g_asrc1[node * H1] = make_float4(acc[0], acc[1], acc[2], acc[3]);
        *(float4*)&g_adst1[node * H1] = make_float4(acc[4], acc[5], acc[6], acc[7]);
    }
}

__global__ void attn2_kernel() {
    __shared__ float sw[2 * F1];
    int tid = threadIdx.x;
    for (int i = tid; i < 2 * F1; i += 256) sw[i] = g_w2[i];
    __syncthreads();
    int node = (blockIdx.x * 256 + tid) >> 5;
    int lane = tid & 31;
    if (node >= N_NODES) return;
    const float* hp = &g_h1r[(size_t)node * F1];
    float ss = 0.0f, sd = 0.0f;
#pragma unroll
    for (int k = 0; k < 3; k++) {
        float2 hv = *(const float2*)&hp[k * 64 + lane * 2];
        float2 wsv = *(const float2*)&sw[k * 64 + lane * 2];
        float2 wdv = *(const float2*)&sw[F1 + k * 64 + lane * 2];
        ss += hv.x * wsv.x + hv.y * wsv.y;
        sd += hv.x * wdv.x + hv.y * wdv.y;
    }
#pragma unroll
    for (int o = 16; o > 0; o >>= 1) {
        ss += __shfl_xor_sync(0xffffffffu, ss, o);
        sd += __shfl_xor_sync(0xffffffffu, sd, o);
    }
    if (lane == 0) {
        g_asrc2[node] = ss;
        g_adst2[node] = sd;
    }
}

// ---------------- R4-proven SGEMM, fp16-only output -------------------------
template <int TBM, int TBN>
__global__ void __launch_bounds__(256) sgemm_kernel(const float* __restrict__ A,
                                                    const float* __restrict__ B,
                                                    __half* __restrict__ Ch,
                                                    int M, int N, int K) {
    const int TBK = 32;
    __shared__ float As[TBK][TBM + 4];
    __shared__ float Bs[TBK][TBN + 4];

    int tid = threadIdx.x;
    int row0 = blockIdx.y * TBM;
    int col0 = blockIdx.x * TBN;
    int tx = tid % (TBN / 4);
    int ty = tid / (TBN / 4);

    float acc[8][4];
#pragma unroll
    for (int i = 0; i < 8; i++)
#pragma unroll
        for (int j = 0; j < 4; j++) acc[i][j] = 0.0f;

    const int A_F4 = TBM * TBK / 4;
    const int B_F4 = TBK * TBN / 4;

    for (int k0 = 0; k0 < K; k0 += TBK) {
#pragma unroll
        for (int it = 0; it < A_F4 / 256; it++) {
            int idA = tid + it * 256;
            int kc = idA % (TBK / 4);
            int r = idA / (TBK / 4);
            int gr = row0 + r;
            float4 v = (gr < M) ? *(const float4*)&A[(size_t)gr * K + k0 + kc * 4]
                                : make_float4(0.f, 0.f, 0.f, 0.f);
            As[kc * 4 + 0][r] = v.x;
            As[kc * 4 + 1][r] = v.y;
            As[kc * 4 + 2][r] = v.z;
            As[kc * 4 + 3][r] = v.w;
        }
#pragma unroll
        for (int it = 0; it < B_F4 / 256; it++) {
            int idB = tid + it * 256;
            int c4 = idB % (TBN / 4);
            int r = idB / (TBN / 4);
            *(float4*)&Bs[r][c4 * 4] = *(const float4*)&B[(size_t)(k0 + r) * N + col0 + c4 * 4];
        }
        __syncthreads();

#pragma unroll
        for (int k = 0; k < TBK; k++) {
            float4 a0 = *(const float4*)&As[k][ty * 8];
            float4 a1 = *(const float4*)&As[k][ty * 8 + 4];
            float4 b = *(const float4*)&Bs[k][tx * 4];
            float av[8] = {a0.x, a0.y, a0.z, a0.w, a1.x, a1.y, a1.z, a1.w};
            float bv[4] = {b.x, b.y, b.z, b.w};
#pragma unroll
            for (int i = 0; i < 8; i++)
#pragma unroll
                for (int j = 0; j < 4; j++) acc[i][j] += av[i] * bv[j];
        }
        __syncthreads();
    }

#pragma unroll
    for (int i = 0; i < 8; i++) {
        int gr = row0 + ty * 8 + i;
        if (gr < M) {
            __half2 h01 = __floats2half2_rn(acc[i][0], acc[i][1]);
            __half2 h23 = __floats2half2_rn(acc[i][2], acc[i][3]);
            *(__half2*)&Ch[(size_t)gr * N + col0 + tx * 4] = h01;
            *(__half2*)&Ch[(size_t)gr * N + col0 + tx * 4 + 2] = h23;
        }
    }
}

// ---------------- layer 1 fused (R9-proven): fp32 softmax, fp16 gather ------
__global__ void gat1_kernel(const float* __restrict__ b1) {
    int node = (blockIdx.x * blockDim.x + threadIdx.x) >> 5;
    int lane = threadIdx.x & 31;
    if (node >= N_NODES) return;
    int start = g_off[node], end = g_off[node + 1];

    float4 ad = *(const float4*)&g_adst1[node * H1];

    float4 den = make_float4(0.f, 0.f, 0.f, 0.f);
    for (int idx = start + lane; idx < end; idx += 32) {
        int src = g_csr_src[idx];
        float4 as = *(const float4*)&g_asrc1[src * H1];
        float4 p;
        p.x = __expf(leaky(as.x + ad.x));
        p.y = __expf(leaky(as.y + ad.y));
        p.z = __expf(leaky(as.z + ad.z));
        p.w = __expf(leaky(as.w + ad.w));
        *(float4*)&g_p[(size_t)idx * 4] = p;
        den.x += p.x; den.y += p.y; den.z += p.z; den.w += p.w;
    }
#pragma unroll
    for (int o = 16; o > 0; o >>= 1) {
        den.x += __shfl_xor_sync(0xffffffffu, den.x, o);
        den.y += __shfl_xor_sync(0xffffffffu, den.y, o);
        den.z += __shfl_xor_sync(0xffffffffu, den.z, o);
        den.w += __shfl_xor_sync(0xffffffffu, den.w, o);
    }
    float inv0 = 1.0f / den.x, inv1 = 1.0f / den.y, inv2 = 1.0f / den.z, inv3 = 1.0f / den.w;

    float acc[6] = {0.f, 0.f, 0.f, 0.f, 0.f, 0.f};
    for (int idx = start; idx < end; idx++) {
        int src = g_csr_src[idx];
        float4 p4 = *(const float4*)&g_p[(size_t)idx * 4];
        float a0 = p4.x * inv0, a1 = p4.y * inv1, a2 = p4.z * inv2, a3 = p4.w * inv3;
        const __half* hp = &g_h1h[(size_t)src * F1];
#pragma unroll
        for (int k = 0; k < 6; k++) {
            int c = k * 32 + lane;
            float al = (c < 48) ? a0 : (c < 96) ? a1 : (c < 144) ? a2 : a3;
            acc[k] += __half2float(hp[c]) * al;
        }
    }
#pragma unroll
    for (int k = 0; k < 6; k++) {
        int c = k * 32 + lane;
        g_h1r[(size_t)node * F1 + c] = fmaxf(acc[k] + b1[c], 0.0f);
    }
}

// ---------------- layer 2 fused (R9-proven): fp32 softmax + pool ------------
__global__ void gat2_kernel(const float* __restrict__ b2) {
    int node = (blockIdx.x * blockDim.x + threadIdx.x) >> 5;
    int lane = threadIdx.x & 31;
    if (node >= N_NODES) return;
    int start = g_off[node], end = g_off[node + 1];

    float ad = g_adst2[node];
    float den = 0.0f;
    for (int idx = start + lane; idx < end; idx += 32) {
        int src = g_csr_src[idx];
        float p = __expf(leaky(g_asrc2[src] + ad));
        g_p[idx] = p;
        den += p;
    }
#pragma unroll
    for (int o = 16; o > 0; o >>= 1) den += __shfl_xor_sync(0xffffffffu, den, o);
    float inv = 1.0f / den;

    float acc[3] = {0.f, 0.f, 0.f};
    for (int idx = start; idx < end; idx++) {
        int src = g_csr_src[idx];
        float alpha = g_p[idx] * inv;
        const __half* hp = &g_h2h[(size_t)src * C2];
#pragma unroll
        for (int k = 0; k < 3; k++) acc[k] += __half2float(hp[k * 32 + lane]) * alpha;
    }
    int gp = g_batch[node] * C2;
#pragma unroll
    for (int k = 0; k < 3; k++) {
        int c = k * 32 + lane;
        float v = fmaxf(acc[k] + b2[c], 0.0f);
        atomicAdd(&g_pool[gp + c], v);
    }
}

// ---------------- final MLP: one block per graph ----------------
__global__ void mlp_kernel(const float* __restrict__ fc1_w, const float* __restrict__ fc1_b,
                           const float* __restrict__ fc2_w, const float* __restrict__ fc2_b,
                           float* __restrict__ out) {
    __shared__ float p[C2];
    __shared__ float z[192];
    int g = blockIdx.x;
    int t = threadIdx.x;
    float inv = 1.0f / fmaxf(g_cnt[g], 1.0f);
    if (t < C2) p[t] = g_pool[g * C2 + t] * inv;
    __syncthreads();
    float acc = fc1_b[t];
#pragma unroll
    for (int k = 0; k < C2; k++) acc += p[k] * fc1_w[k * 192 + t];
    z[t] = fmaxf(acc, 0.0f);
    __syncthreads();
    if (t < C2) {
        float o = fc2_b[t];
#pragma unroll
        for (int k = 0; k < 192; k++) o += z[k] * fc2_w[k * C2 + t];
        out[g * C2 + t] = o;
    }
}

// ---------------- host launch (two-stream overlap, capture-legal) ----------
extern "C" void kernel_launch(void* const* d_in, const int* in_sizes, int n_in,
                              void* d_out, int out_size) {
    const float* x = (const float*)d_in[0];
    const void* ei_raw = d_in[1];
    const void* batch_raw = d_in[2];
    const float* W1 = (const float*)d_in[3];
    const float* a_src1 = (const float*)d_in[4];
    const float* a_dst1 = (const float*)d_in[5];
    const float* b1 = (const float*)d_in[6];
    const float* W2 = (const float*)d_in[7];
    const float* a_src2 = (const float*)d_in[8];
    const float* a_dst2 = (const float*)d_in[9];
    const float* b2 = (const float*)d_in[10];
    const float* fc1_w = (const float*)d_in[11];
    const float* fc1_b = (const float*)d_in[12];
    const float* fc2_w = (const float*)d_in[13];
    const float* fc2_b = (const float*)d_in[14];
    float* out = (float*)d_out;

    int E0 = in_sizes[1] / 2;
    int Etot = E0 + N_NODES;

    float* h1rp;
    __half *h1hp, *h2hp;
    cudaGetSymbolAddress((void**)&h1rp, g_h1r);
    cudaGetSymbolAddress((void**)&h1hp, g_h1h);
    cudaGetSymbolAddress((void**)&h2hp, g_h2h);

    cudaStream_t sB;
    cudaStreamCreateWithFlags(&sB, cudaStreamNonBlocking);
    cudaEvent_t evFork, evPre, evJoin, evFork2, evJoin2;
    cudaEventCreateWithFlags(&evFork, cudaEventDisableTiming);
    cudaEventCreateWithFlags(&evPre, cudaEventDisableTiming);
    cudaEventCreateWithFlags(&evJoin, cudaEventDisableTiming);
    cudaEventCreateWithFlags(&evFork2, cudaEventDisableTiming);
    cudaEventCreateWithFlags(&evJoin2, cudaEventDisableTiming);

    cudaEventRecord(evFork, 0);
    cudaStreamWaitEvent(sB, evFork, 0);

    // ---- default: attention-vector precompute (needed by attn kernels on sB)
    precomp1_kernel<<<1, 1024>>>(W1, a_src1, a_dst1);
    precomp2_kernel<<<1, 384>>>(W2, a_src2, a_dst2);
    cudaEventRecord(evPre, 0);

    // ---- stream B: CSR build + batch decode + attn1 ----
    init_kernel<<<256, 256, 0, sB>>>();
    sniff_kernel<<<1, 256, 0, sB>>>((const unsigned int*)ei_raw);
    decode_edges<<<(Etot + 255) / 256, 256, 0, sB>>>(ei_raw, E0);
    decode_batch<<<(N_NODES + 255) / 256, 256, 0, sB>>>(batch_raw);
    scan_kernel<<<1, 1024, 0, sB>>>();
    scatter_kernel<<<(Etot + 255) / 256, 256, 0, sB>>>(Etot);
    cudaStreamWaitEvent(sB, evPre, 0);
    attn1_kernel<<<(N_NODES * 32 + 255) / 256, 256, 0, sB>>>(x);
    cudaEventRecord(evJoin, sB);

    // ---- default: GEMM1 (fp16 table only) ----
    {
        dim3 grid(F1 / 64, (N_NODES + 127) / 128);
        sgemm_kernel<128, 64><<<grid, 256>>>(x, W1, h1hp, N_NODES, F1, D_IN);
    }
    cudaStreamWaitEvent(0, evJoin, 0);
    gat1_kernel<<<(N_NODES + 7) / 8, 256>>>(b1);
    cudaEventRecord(evFork2, 0);

    // ---- stream B: attn2 (reads h1r) concurrent with GEMM2 ----
    cudaStreamWaitEvent(sB, evFork2, 0);
    attn2_kernel<<<(N_NODES * 32 + 255) / 256, 256, 0, sB>>>();
    cudaEventRecord(evJoin2, sB);

    // ---- default: GEMM2 (fp16 table only) ----
    {
        dim3 grid(C2 / 32, (N_NODES + 255) / 256);
        sgemm_kernel<256, 32><<<grid, 256>>>(h1rp, W2, h2hp, N_NODES, C2, F1);
    }
    cudaStreamWaitEvent(0, evJoin2, 0);
    gat2_kernel<<<(N_NODES + 7) / 8, 256>>>(b2);

    // MLP head
    mlp_kernel<<<NUM_GRAPHS, 192>>>(fc1_w, fc1_b, fc2_w, fc2_b, out);
}

// round 12
// speedup vs baseline: 1.1099x; 1.1099x over previous
#include <cuda_runtime.h>
#include <cuda_fp16.h>
#include <math.h>

#define N_NODES 100000
#define NUM_GRAPHS 128
#define H1 4
#define C1 48
#define F1 192   // H1*C1
#define C2 96
#define D_IN 128
#define NEG_SLOPE 0.2f
#define E_MAX 1750000   // raw edges (1.6M) + self loops (100k) with slack

// ---------------- scratch (device globals; no allocation) ----------------
__device__ __half g_h1h[N_NODES * F1];      // fp16 gather table (layer 1)
__device__ float g_h1r[N_NODES * F1];       // layer1 output (relu'd, fp32)
__device__ __half g_h2h[N_NODES * C2];      // fp16 gather table (layer 2)
__device__ float g_asrc1[N_NODES * H1];
__device__ float g_adst1[N_NODES * H1];
__device__ float g_asrc2[N_NODES];
__device__ float g_adst2[N_NODES];
__device__ float g_pool[NUM_GRAPHS * C2];
__device__ float g_cnt[NUM_GRAPHS];
__device__ int g_src[E_MAX];
__device__ int g_dst[E_MAX];
__device__ int g_batch[N_NODES];
__device__ int g_is64;
__device__ int g_deg[N_NODES];
__device__ int g_off[N_NODES + 1];
__device__ int g_cur[N_NODES];
__device__ int g_csr_src[E_MAX];
__device__ float g_p[E_MAX * H1];

__device__ __forceinline__ float leaky(float s) {
    return s > 0.0f ? s : NEG_SLOPE * s;
}

// ---------------- init (zero counters only; stream B) ----------------
__global__ void init_kernel() {
    int i = blockIdx.x * blockDim.x + threadIdx.x;
    int stride = gridDim.x * blockDim.x;
    for (int k = i; k < N_NODES; k += stride) g_deg[k] = 0;
    for (int k = i; k < NUM_GRAPHS * C2; k += stride) g_pool[k] = 0.0f;
    for (int k = i; k < NUM_GRAPHS; k += stride) g_cnt[k] = 0.0f;
}

// zero attention accumulators (default stream, before GEMM1)
__global__ void zero_attn_kernel() {
    int i = blockIdx.x * blockDim.x + threadIdx.x;
    if (i < N_NODES * H1) {
        g_asrc1[i] = 0.0f;
        g_adst1[i] = 0.0f;
    }
    if (i < N_NODES) {
        g_asrc2[i] = 0.0f;
        g_adst2[i] = 0.0f;
    }
}

// ---------------- dtype sniff: int64 vs int32 index buffers ----------------
__global__ void sniff_kernel(const unsigned int* __restrict__ w) {
    __shared__ int any_nonzero;
    if (threadIdx.x == 0) any_nonzero = 0;
    __syncthreads();
    for (int i = threadIdx.x; i < 256; i += blockDim.x) {
        if (w[2 * i + 1] != 0u) any_nonzero = 1;
    }
    __syncthreads();
    if (threadIdx.x == 0) g_is64 = (any_nonzero == 0) ? 1 : 0;
}

__global__ void decode_edges(const void* __restrict__ ei_raw, int E0) {
    int e = blockIdx.x * blockDim.x + threadIdx.x;
    int Etot = E0 + N_NODES;
    if (e >= Etot) return;
    int src, dst;
    if (e < E0) {
        if (g_is64) {
            const long long* p = (const long long*)ei_raw;
            src = (int)p[e];
            dst = (int)p[E0 + e];
        } else {
            const int* p = (const int*)ei_raw;
            src = p[e];
            dst = p[E0 + e];
        }
    } else {
        src = dst = e - E0;
    }
    g_src[e] = src;
    g_dst[e] = dst;
    atomicAdd(&g_deg[dst], 1);
}

__global__ void decode_batch(const void* __restrict__ b_raw) {
    __shared__ int hist[NUM_GRAPHS];
    for (int i = threadIdx.x; i < NUM_GRAPHS; i += blockDim.x) hist[i] = 0;
    __syncthreads();
    int n = blockIdx.x * blockDim.x + threadIdx.x;
    if (n < N_NODES) {
        int b = g_is64 ? (int)((const long long*)b_raw)[n] : ((const int*)b_raw)[n];
        g_batch[n] = b;
        atomicAdd(&hist[b], 1);
    }
    __syncthreads();
    for (int i = threadIdx.x; i < NUM_GRAPHS; i += blockDim.x)
        if (hist[i]) atomicAdd(&g_cnt[i], (float)hist[i]);
}

__global__ void scan_kernel() {
    __shared__ int part[1024];
    int t = threadIdx.x;
    const int CH = (N_NODES + 1023) / 1024;
    int lo = t * CH, hi = min(lo + CH, N_NODES);
    int s = 0;
    for (int i = lo; i < hi; i++) s += g_deg[i];
    part[t] = s;
    __syncthreads();
    for (int o = 1; o < 1024; o <<= 1) {
        int v = (t >= o) ? part[t - o] : 0;
        __syncthreads();
        part[t] += v;
        __syncthreads();
    }
    int base = (t > 0) ? part[t - 1] : 0;
    for (int i = lo; i < hi; i++) {
        g_off[i] = base;
        g_cur[i] = base;
        base += g_deg[i];
    }
    if (t == 1023) g_off[N_NODES] = part[1023];
}

__global__ void scatter_kernel(int Etot) {
    int e = blockIdx.x * blockDim.x + threadIdx.x;
    if (e >= Etot) return;
    int pos = atomicAdd(&g_cur[g_dst[e]], 1);
    g_csr_src[pos] = g_src[e];
}

// ---------------- GEMM1: [M,128]@[128,192] -> fp16 table + fused attn1 ------
// TBM=128, TBN=64, 256 threads, 8x4 microtile. Head boundaries (48/96/144) are
// multiples of 4 => each thread's 4 cols lie in exactly one head.
__global__ void __launch_bounds__(256) sgemm1_kernel(const float* __restrict__ A,
                                                     const float* __restrict__ B,
                                                     __half* __restrict__ Ch,
                                                     const float* __restrict__ a_src,
                                                     const float* __restrict__ a_dst,
                                                     int M) {
    const int TBM = 128, TBN = 64, TBK = 32, N = F1, K = D_IN;
    __shared__ float As[TBK][TBM + 4];   // 4224 floats; reused for attn reduce
    __shared__ float Bs[TBK][TBN + 4];

    int tid = threadIdx.x;
    int row0 = blockIdx.y * TBM;
    int col0 = blockIdx.x * TBN;
    int tx = tid % 16;
    int ty = tid / 16;

    float acc[8][4];
#pragma unroll
    for (int i = 0; i < 8; i++)
#pragma unroll
        for (int j = 0; j < 4; j++) acc[i][j] = 0.0f;

    for (int k0 = 0; k0 < K; k0 += TBK) {
#pragma unroll
        for (int it = 0; it < 4; it++) {  // 128*32/4/256 = 4
            int idA = tid + it * 256;
            int kc = idA % 8;
            int r = idA / 8;
            int gr = row0 + r;
            float4 v = (gr < M) ? *(const float4*)&A[(size_t)gr * K + k0 + kc * 4]
                                : make_float4(0.f, 0.f, 0.f, 0.f);
            As[kc * 4 + 0][r] = v.x;
            As[kc * 4 + 1][r] = v.y;
            As[kc * 4 + 2][r] = v.z;
            As[kc * 4 + 3][r] = v.w;
        }
#pragma unroll
        for (int it = 0; it < 2; it++) {  // 32*64/4/256 = 2
            int idB = tid + it * 256;
            int c4 = idB % 16;
            int r = idB / 16;
            *(float4*)&Bs[r][c4 * 4] = *(const float4*)&B[(size_t)(k0 + r) * N + col0 + c4 * 4];
        }
        __syncthreads();

#pragma unroll
        for (int k = 0; k < TBK; k++) {
            float4 a0 = *(const float4*)&As[k][ty * 8];
            float4 a1 = *(const float4*)&As[k][ty * 8 + 4];
            float4 b = *(const float4*)&Bs[k][tx * 4];
            float av[8] = {a0.x, a0.y, a0.z, a0.w, a1.x, a1.y, a1.z, a1.w};
            float bv[4] = {b.x, b.y, b.z, b.w};
#pragma unroll
            for (int i = 0; i < 8; i++)
#pragma unroll
                for (int j = 0; j < 4; j++) acc[i][j] += av[i] * bv[j];
        }
        __syncthreads();
    }

    // fp16 table store
#pragma unroll
    for (int i = 0; i < 8; i++) {
        int gr = row0 + ty * 8 + i;
        if (gr < M) {
            __half2 h01 = __floats2half2_rn(acc[i][0], acc[i][1]);
            __half2 h23 = __floats2half2_rn(acc[i][2], acc[i][3]);
            *(__half2*)&Ch[(size_t)gr * N + col0 + tx * 4] = h01;
            *(__half2*)&Ch[(size_t)gr * N + col0 + tx * 4 + 2] = h23;
        }
    }

    // fused attention partials: per-thread dot with a_src/a_dst slices
    int cbase = col0 + tx * 4;
    float asv[4], adv[4];
#pragma unroll
    for (int j = 0; j < 4; j++) {
        asv[j] = a_src[cbase + j];
        adv[j] = a_dst[cbase + j];
    }
    float* sredS = &As[0][0];          // [128][16]
    float* sredD = sredS + 2048;
#pragma unroll
    for (int i = 0; i < 8; i++) {
        float ps = acc[i][0] * asv[0] + acc[i][1] * asv[1] + acc[i][2] * asv[2] + acc[i][3] * asv[3];
        float pd = acc[i][0] * adv[0] + acc[i][1] * adv[1] + acc[i][2] * adv[2] + acc[i][3] * adv[3];
        sredS[(ty * 8 + i) * 16 + tx] = ps;
        sredD[(ty * 8 + i) * 16 + tx] = pd;
    }
    __syncthreads();

    if (tid < 128) {
        int gr = row0 + tid;
        if (gr < M) {
            int h0 = col0 / 48;
            int gb = (48 * (h0 + 1) - col0) / 4;   // first tx-group of next head
            if (gb > 16) gb = 16;
            float s0 = 0.f, d0 = 0.f, s1 = 0.f, d1 = 0.f;
            for (int g = 0; g < gb; g++) {
                s0 += sredS[tid * 16 + g];
                d0 += sredD[tid * 16 + g];
            }
            for (int g = gb; g < 16; g++) {
                s1 += sredS[tid * 16 + g];
                d1 += sredD[tid * 16 + g];
            }
            atomicAdd(&g_asrc1[gr * H1 + h0], s0);
            atomicAdd(&g_adst1[gr * H1 + h0], d0);
            if (gb < 16) {
                atomicAdd(&g_asrc1[gr * H1 + h0 + 1], s1);
                atomicAdd(&g_adst1[gr * H1 + h0 + 1], d1);
            }
        }
    }
}

// ---------------- GEMM2: [M,192]@[192,96] -> fp16 table + fused attn2 -------
// TBM=256, TBN=32, 256 threads (tx=0..7, ty=0..31); single head of 96 cols.
__global__ void __launch_bounds__(256) sgemm2_kernel(const float* __restrict__ A,
                                                     const float* __restrict__ B,
                                                     __half* __restrict__ Ch,
                                                     const float* __restrict__ a_src,
                                                     const float* __restrict__ a_dst,
                                                     int M) {
    const int TBM = 256, TBN = 32, TBK = 32, N = C2, K = F1;
    __shared__ float As[TBK][TBM + 4];
    __shared__ float Bs[TBK][TBN + 4];

    int tid = threadIdx.x;
    int row0 = blockIdx.y * TBM;
    int col0 = blockIdx.x * TBN;
    int tx = tid % 8;
    int ty = tid / 8;

    float acc[8][4];
#pragma unroll
    for (int i = 0; i < 8; i++)
#pragma unroll
        for (int j = 0; j < 4; j++) acc[i][j] = 0.0f;

    for (int k0 = 0; k0 < K; k0 += TBK) {
#pragma unroll
        for (int it = 0; it < 8; it++) {  // 256*32/4/256 = 8
            int idA = tid + it * 256;
            int kc = idA % 8;
            int r = idA / 8;
            int gr = row0 + r;
            float4 v = (gr < M) ? *(const float4*)&A[(size_t)gr * K + k0 + kc * 4]
                                : make_float4(0.f, 0.f, 0.f, 0.f);
            As[kc * 4 + 0][r] = v.x;
            As[kc * 4 + 1][r] = v.y;
            As[kc * 4 + 2][r] = v.z;
            As[kc * 4 + 3][r] = v.w;
        }
        {                                  // 32*32/4/256 = 1
            int c4 = tid % 8;
            int r = tid / 8;
            *(float4*)&Bs[r][c4 * 4] = *(const float4*)&B[(size_t)(k0 + r) * N + col0 + c4 * 4];
        }
        __syncthreads();

#pragma unroll
        for (int k = 0; k < TBK; k++) {
            float4 a0 = *(const float4*)&As[k][ty * 8];
            float4 a1 = *(const float4*)&As[k][ty * 8 + 4];
            float4 b = *(const float4*)&Bs[k][tx * 4];
            float av[8] = {a0.x, a0.y, a0.z, a0.w, a1.x, a1.y, a1.z, a1.w};
            float bv[4] = {b.x, b.y, b.z, b.w};
#pragma unroll
            for (int i = 0; i < 8; i++)
#pragma unroll
                for (int j = 0; j < 4; j++) acc[i][j] += av[i] * bv[j];
        }
        __syncthreads();
    }

    int cbase = col0 + tx * 4;
    float asv[4], adv[4];
#pragma unroll
    for (int j = 0; j < 4; j++) {
        asv[j] = a_src[cbase + j];
        adv[j] = a_dst[cbase + j];
    }

#pragma unroll
    for (int i = 0; i < 8; i++) {
        int gr = row0 + ty * 8 + i;
        float ps = acc[i][0] * asv[0] + acc[i][1] * asv[1] + acc[i][2] * asv[2] + acc[i][3] * asv[3];
        float pd = acc[i][0] * adv[0] + acc[i][1] * adv[1] + acc[i][2] * adv[2] + acc[i][3] * adv[3];
        // reduce across tx (8 lanes, same ty within warp)
#pragma unroll
        for (int o = 1; o < 8; o <<= 1) {
            ps += __shfl_xor_sync(0xffffffffu, ps, o);
            pd += __shfl_xor_sync(0xffffffffu, pd, o);
        }
        if (gr < M) {
            __half2 h01 = __floats2half2_rn(acc[i][0], acc[i][1]);
            __half2 h23 = __floats2half2_rn(acc[i][2], acc[i][3]);
            *(__half2*)&Ch[(size_t)gr * N + col0 + tx * 4] = h01;
            *(__half2*)&Ch[(size_t)gr * N + col0 + tx * 4 + 2] = h23;
            if (tx == 0) {
                atomicAdd(&g_asrc2[gr], ps);
                atomicAdd(&g_adst2[gr], pd);
            }
        }
    }
}

// ---------------- layer 1 fused (R9-proven): fp32 softmax, fp16 gather ------
__global__ void gat1_kernel(const float* __restrict__ b1) {
    int node = (blockIdx.x * blockDim.x + threadIdx.x) >> 5;
    int lane = threadIdx.x & 31;
    if (node >= N_NODES) return;
    int start = g_off[node], end = g_off[node + 1];

    float4 ad = *(const float4*)&g_adst1[node * H1];

    float4 den = make_float4(0.f, 0.f, 0.f, 0.f);
    for (int idx = start + lane; idx < end; idx += 32) {
        int src = g_csr_src[idx];
        float4 as = *(const float4*)&g_asrc1[src * H1];
        float4 p;
        p.x = __expf(leaky(as.x + ad.x));
        p.y = __expf(leaky(as.y + ad.y));
        p.z = __expf(leaky(as.z + ad.z));
        p.w = __expf(leaky(as.w + ad.w));
        *(float4*)&g_p[(size_t)idx * 4] = p;
        den.x += p.x; den.y += p.y; den.z += p.z; den.w += p.w;
    }
#pragma unroll
    for (int o = 16; o > 0; o >>= 1) {
        den.x += __shfl_xor_sync(0xffffffffu, den.x, o);
        den.y += __shfl_xor_sync(0xffffffffu, den.y, o);
        den.z += __shfl_xor_sync(0xffffffffu, den.z, o);
        den.w += __shfl_xor_sync(0xffffffffu, den.w, o);
    }
    float inv0 = 1.0f / den.x, inv1 = 1.0f / den.y, inv2 = 1.0f / den.z, inv3 = 1.0f / den.w;

    float acc[6] = {0.f, 0.f, 0.f, 0.f, 0.f, 0.f};
    for (int idx = start; idx < end; idx++) {
        int src = g_csr_src[idx];
        float4 p4 = *(const float4*)&g_p[(size_t)idx * 4];
        float a0 = p4.x * inv0, a1 = p4.y * inv1, a2 = p4.z * inv2, a3 = p4.w * inv3;
        const __half* hp = &g_h1h[(size_t)src * F1];
#pragma unroll
        for (int k = 0; k < 6; k++) {
            int c = k * 32 + lane;
            float al = (c < 48) ? a0 : (c < 96) ? a1 : (c < 144) ? a2 : a3;
            acc[k] += __half2float(hp[c]) * al;
        }
    }
#pragma unroll
    for (int k = 0; k < 6; k++) {
        int c = k * 32 + lane;
        g_h1r[(size_t)node * F1 + c] = fmaxf(acc[k] + b1[c], 0.0f);
    }
}

// ---------------- layer 2 fused (R9-proven): fp32 softmax + pool ------------
__global__ void gat2_kernel(const float* __restrict__ b2) {
    int node = (blockIdx.x * blockDim.x + threadIdx.x) >> 5;
    int lane = threadIdx.x & 31;
    if (node >= N_NODES) return;
    int start = g_off[node], end = g_off[node + 1];

    float ad = g_adst2[node];
    float den = 0.0f;
    for (int idx = start + lane; idx < end; idx += 32) {
        int src = g_csr_src[idx];
        float p = __expf(leaky(g_asrc2[src] + ad));
        g_p[idx] = p;
        den += p;
    }
#pragma unroll
    for (int o = 16; o > 0; o >>= 1) den += __shfl_xor_sync(0xffffffffu, den, o);
    float inv = 1.0f / den;

    float acc[3] = {0.f, 0.f, 0.f};
    for (int idx = start; idx < end; idx++) {
        int src = g_csr_src[idx];
        float alpha = g_p[idx] * inv;
        const __half* hp = &g_h2h[(size_t)src * C2];
#pragma unroll
        for (int k = 0; k < 3; k++) acc[k] += __half2float(hp[k * 32 + lane]) * alpha;
    }
    int gp = g_batch[node] * C2;
#pragma unroll
    for (int k = 0; k < 3; k++) {
        int c = k * 32 + lane;
        float v = fmaxf(acc[k] + b2[c], 0.0f);
        atomicAdd(&g_pool[gp + c], v);
    }
}

// ---------------- final MLP: one block per graph ----------------
__global__ void mlp_kernel(const float* __restrict__ fc1_w, const float* __restrict__ fc1_b,
                           const float* __restrict__ fc2_w, const float* __restrict__ fc2_b,
                           float* __restrict__ out) {
    __shared__ float p[C2];
    __shared__ float z[192];
    int g = blockIdx.x;
    int t = threadIdx.x;
    float inv = 1.0f / fmaxf(g_cnt[g], 1.0f);
    if (t < C2) p[t] = g_pool[g * C2 + t] * inv;
    __syncthreads();
    float acc = fc1_b[t];
#pragma unroll
    for (int k = 0; k < C2; k++) acc += p[k] * fc1_w[k * 192 + t];
    z[t] = fmaxf(acc, 0.0f);
    __syncthreads();
    if (t < C2) {
        float o = fc2_b[t];
#pragma unroll
        for (int k = 0; k < 192; k++) o += z[k] * fc2_w[k * C2 + t];
        out[g * C2 + t] = o;
    }
}

// ---------------- host launch (two-stream overlap, capture-legal) ----------
extern "C" void kernel_launch(void* const* d_in, const int* in_sizes, int n_in,
                              void* d_out, int out_size) {
    const float* x = (const float*)d_in[0];
    const void* ei_raw = d_in[1];
    const void* batch_raw = d_in[2];
    const float* W1 = (const float*)d_in[3];
    const float* a_src1 = (const float*)d_in[4];
    const float* a_dst1 = (const float*)d_in[5];
    const float* b1 = (const float*)d_in[6];
    const float* W2 = (const float*)d_in[7];
    const float* a_src2 = (const float*)d_in[8];
    const float* a_dst2 = (const float*)d_in[9];
    const float* b2 = (const float*)d_in[10];
    const float* fc1_w = (const float*)d_in[11];
    const float* fc1_b = (const float*)d_in[12];
    const float* fc2_w = (const float*)d_in[13];
    const float* fc2_b = (const float*)d_in[14];
    float* out = (float*)d_out;

    int E0 = in_sizes[1] / 2;
    int Etot = E0 + N_NODES;

    float* h1rp;
    __half *h1hp, *h2hp;
    cudaGetSymbolAddress((void**)&h1rp, g_h1r);
    cudaGetSymbolAddress((void**)&h1hp, g_h1h);
    cudaGetSymbolAddress((void**)&h2hp, g_h2h);

    cudaStream_t sB;
    cudaStreamCreateWithFlags(&sB, cudaStreamNonBlocking);
    cudaEvent_t evFork, evJoin;
    cudaEventCreateWithFlags(&evFork, cudaEventDisableTiming);
    cudaEventCreateWithFlags(&evJoin, cudaEventDisableTiming);

    cudaEventRecord(evFork, 0);
    cudaStreamWaitEvent(sB, evFork, 0);

    // ---- stream B: CSR build + batch decode ----
    init_kernel<<<256, 256, 0, sB>>>();
    sniff_kernel<<<1, 256, 0, sB>>>((const unsigned int*)ei_raw);
    decode_edges<<<(Etot + 255) / 256, 256, 0, sB>>>(ei_raw, E0);
    decode_batch<<<(N_NODES + 255) / 256, 256, 0, sB>>>(batch_raw);
    scan_kernel<<<1, 1024, 0, sB>>>();
    scatter_kernel<<<(Etot + 255) / 256, 256, 0, sB>>>(Etot);
    cudaEventRecord(evJoin, sB);

    // ---- default: zero attn accumulators, GEMM1 (+fused attn1) ----
    zero_attn_kernel<<<(N_NODES * H1 + 255) / 256, 256>>>();
    {
        dim3 grid(F1 / 64, (N_NODES + 127) / 128);
        sgemm1_kernel<<<grid, 256>>>(x, W1, h1hp, a_src1, a_dst1, N_NODES);
    }
    cudaStreamWaitEvent(0, evJoin, 0);
    gat1_kernel<<<(N_NODES + 7) / 8, 256>>>(b1);

    // ---- default: GEMM2 (+fused attn2), gat2 ----
    {
        dim3 grid(C2 / 32, (N_NODES + 255) / 256);
        sgemm2_kernel<<<grid, 256>>>(h1rp, W2, h2hp, a_src2, a_dst2, N_NODES);
    }
    gat2_kernel<<<(N_NODES + 7) / 8, 256>>>(b2);

    // MLP head
    mlp_kernel<<<NUM_GRAPHS, 192>>>(fc1_w, fc1_b, fc2_w, fc2_b, out);
}